// round 6
// baseline (speedup 1.0000x reference)
#include <cuda_runtime.h>
#include <cuda_bf16.h>
#include <cstdint>

// ---------------------------------------------------------------------------
// Problem constants
// ---------------------------------------------------------------------------
#define BATCH   8192
#define CDIM    1024
#define NPROJ   4096
#define KPROJ   1024
#define NFC     1024
#define KFC     4096

typedef unsigned short ushort_t;

// ---------------------------------------------------------------------------
// Device scratch (bf16 hi/lo pairs stored as ushort bit patterns)
// ---------------------------------------------------------------------------
__device__ ushort_t g_Wqh[4096u * 1024u], g_Wql[4096u * 1024u];
__device__ ushort_t g_Wkh[4096u * 1024u], g_Wkl[4096u * 1024u];
__device__ ushort_t g_Wvh[4096u * 1024u], g_Wvl[4096u * 1024u];
__device__ ushort_t g_Wfh[1024u * 4096u], g_Wfl[1024u * 4096u];
__device__ ushort_t g_qh [(size_t)BATCH * 1024u], g_ql [(size_t)BATCH * 1024u];
__device__ ushort_t g_kh [(size_t)BATCH * 1024u], g_kl [(size_t)BATCH * 1024u];
__device__ ushort_t g_vh [(size_t)BATCH * 1024u], g_vl [(size_t)BATCH * 1024u];
__device__ float    g_Yq [(size_t)BATCH * 4096u];
__device__ float    g_Yk [(size_t)BATCH * 4096u];
__device__ float    g_Yv [(size_t)BATCH * 4096u];
__device__ ushort_t g_Zh [(size_t)BATCH * 4096u], g_Zl [(size_t)BATCH * 4096u];
__device__ float    g_attn_dummy[(size_t)BATCH * 512u];

// ---------------------------------------------------------------------------
// Helpers
// ---------------------------------------------------------------------------
__device__ __forceinline__ uint32_t smem_to_u32(const void* p) {
    uint32_t a;
    asm("{ .reg .u64 t; cvta.to.shared.u64 t, %1; cvt.u32.u64 %0, t; }" : "=r"(a) : "l"(p));
    return a;
}
__device__ __forceinline__ ushort_t bf16_rn_bits(float x) {
    ushort_t r;
    asm("{.reg .b16 t; cvt.rn.bf16.f32 t, %1; mov.b16 %0, t;}" : "=h"(r) : "f"(x));
    return r;
}

#define LDM_X4(r0, r1, r2, r3, addr) \
    asm volatile("ldmatrix.sync.aligned.m8n8.x4.shared.b16 {%0,%1,%2,%3}, [%4];" \
        : "=r"(r0), "=r"(r1), "=r"(r2), "=r"(r3) : "r"(addr))

__device__ __forceinline__ void mma16816(float* c, const uint32_t* a, const uint32_t* b) {
    asm volatile(
        "mma.sync.aligned.m16n8k16.row.col.f32.bf16.bf16.f32 "
        "{%0,%1,%2,%3}, {%4,%5,%6,%7}, {%8,%9}, {%0,%1,%2,%3};"
        : "+f"(c[0]), "+f"(c[1]), "+f"(c[2]), "+f"(c[3])
        : "r"(a[0]), "r"(a[1]), "r"(a[2]), "r"(a[3]), "r"(b[0]), "r"(b[1]));
}

// ---------------------------------------------------------------------------
// Circulant expansion fused with bf16 hi/lo split
//   e indexes dst[(o*8+g1)*(I*8) + i*8+g2] = w[o, i, (g1-g2)&7]
// ---------------------------------------------------------------------------
__global__ void expand_split_kernel(const float* __restrict__ src,
                                    ushort_t* __restrict__ dh,
                                    ushort_t* __restrict__ dl,
                                    int O, int I, int sh) {
    int total = O * I * 64;
    int mask = I * 8 - 1;
    for (int e = blockIdx.x * blockDim.x + threadIdx.x; e < total;
         e += gridDim.x * blockDim.x) {
        int n  = e >> sh;
        int kk = e & mask;
        int o  = n >> 3, g1 = n & 7;
        int i  = kk >> 3, g2 = kk & 7;
        float x = src[(o * I + i) * 8 + ((g1 - g2) & 7)];
        uint32_t u = __float_as_uint(x);
        dh[e] = (ushort_t)(u >> 16);
        dl[e] = bf16_rn_bits(x - __uint_as_float(u & 0xffff0000u));
    }
}

// ---------------------------------------------------------------------------
// Activation split: fp32 -> bf16 hi/lo (vectorized)
// ---------------------------------------------------------------------------
__global__ void split_act_kernel(const float4* __restrict__ x,
                                 ushort_t* __restrict__ xh,
                                 ushort_t* __restrict__ xl, int n4) {
    int i = blockIdx.x * blockDim.x + threadIdx.x;
    if (i >= n4) return;
    float4 v = x[i];
    uint32_t ux = __float_as_uint(v.x), uy = __float_as_uint(v.y);
    uint32_t uz = __float_as_uint(v.z), uw = __float_as_uint(v.w);
    uint2 hv;
    hv.x = __byte_perm(ux, uy, 0x7632);
    hv.y = __byte_perm(uz, uw, 0x7632);
    float lx = v.x - __uint_as_float(ux & 0xffff0000u);
    float ly = v.y - __uint_as_float(uy & 0xffff0000u);
    float lz = v.z - __uint_as_float(uz & 0xffff0000u);
    float lw = v.w - __uint_as_float(uw & 0xffff0000u);
    uint2 lv;
    asm("cvt.rn.bf16x2.f32 %0, %1, %2;" : "=r"(lv.x) : "f"(ly), "f"(lx));
    asm("cvt.rn.bf16x2.f32 %0, %1, %2;" : "=r"(lv.y) : "f"(lw), "f"(lz));
    reinterpret_cast<uint2*>(xh)[i] = hv;
    reinterpret_cast<uint2*>(xl)[i] = lv;
}

// ---------------------------------------------------------------------------
// bf16 split-2 3-pass GEMM, all-bf16 mainloop:
//   C[M,N] = (Ah+Al)[M,K] * (Bh+Bl)[N,K]^T (+bias[n/8]) (+residual)
// 128x128 tile, BK=32, 256 thr (8 warps 2x4, warp tile 64x32),
// cp.async double-buffer + ldmatrix fragment loads.
// ---------------------------------------------------------------------------
#define TM 128
#define TN 128
#define TK 32
#define ROWB 80u                        // bytes per smem row (40 halves)
#define TILE_B (128u * ROWB)            // 10240
#define STAGE_B (4u * TILE_B)           // 40960
#define GEMM_SMEM_BYTES (2u * STAGE_B)  // 81920

__global__ __launch_bounds__(256)
void gemm_bf16ldm(const ushort_t* __restrict__ Ah_g, const ushort_t* __restrict__ Al_g,
                  const ushort_t* __restrict__ Bh_g, const ushort_t* __restrict__ Bl_g,
                  float* __restrict__ C, int N, int K,
                  const float* __restrict__ bias, const float* __restrict__ residual)
{
    extern __shared__ char smraw[];
    uint32_t sb = smem_to_u32(smraw);
    const int tid = threadIdx.x, wid = tid >> 5, lane = tid & 31;
    const int wm = wid >> 2, wn = wid & 3;
    const size_t m0 = (size_t)blockIdx.y * TM;
    const size_t n0 = (size_t)blockIdx.x * TN;

    float acc[4][4][4];
#pragma unroll
    for (int i = 0; i < 4; i++)
#pragma unroll
        for (int j = 0; j < 4; j++)
#pragma unroll
            for (int r = 0; r < 4; r++) acc[i][j][r] = 0.f;

    // cp.async geometry: thread covers 8 sixteen-byte segs per chunk.
    // t in 0..7 -> tile = t>>1 (Ah,Al,Bh,Bl), row = (t&1)*64 + tid/4, seg = tid&3.
    const int rr  = tid >> 2;
    const int seg = tid & 3;
    auto issue = [&](int c, int s) {
        int k0 = c * TK;
        uint32_t stg = sb + (uint32_t)s * STAGE_B;
#pragma unroll
        for (int t = 0; t < 8; t++) {
            const int tile = t >> 1;
            const int r = ((t & 1) << 6) + rr;
            const ushort_t* sp;
            size_t rb;
            if      (tile == 0) { sp = Ah_g; rb = m0; }
            else if (tile == 1) { sp = Al_g; rb = m0; }
            else if (tile == 2) { sp = Bh_g; rb = n0; }
            else                { sp = Bl_g; rb = n0; }
            const ushort_t* src = sp + (rb + (size_t)r) * (size_t)K + k0 + seg * 8;
            uint32_t dst = stg + (uint32_t)tile * TILE_B + (uint32_t)r * ROWB + (uint32_t)seg * 16u;
            asm volatile("cp.async.cg.shared.global [%0], [%1], 16;"
                         :: "r"(dst), "l"(src) : "memory");
        }
        asm volatile("cp.async.commit_group;" ::: "memory");
    };

    const int NC = K / TK;
    issue(0, 0);

    const uint32_t lA  = (uint32_t)(lane & 15);
    const uint32_t sgo = (uint32_t)(lane >> 4) * 16u;

    for (int c = 0; c < NC; c++) {
        int s = c & 1;
        if (c + 1 < NC) {
            issue(c + 1, (c + 1) & 1);
            asm volatile("cp.async.wait_group 1;" ::: "memory");
        } else {
            asm volatile("cp.async.wait_group 0;" ::: "memory");
        }
        __syncthreads();

        uint32_t stg = sb + (uint32_t)s * STAGE_B;
#pragma unroll
        for (int ks = 0; ks < 2; ks++) {
            uint32_t kso = (uint32_t)ks * 32u;
            uint32_t ah[4][4], al[4][4], bh[4][2], bl[4][2];
#pragma unroll
            for (int i = 0; i < 4; i++) {
                uint32_t ad = stg + (uint32_t)(wm * 64 + i * 16 + lA) * ROWB + kso + sgo;
                LDM_X4(ah[i][0], ah[i][1], ah[i][2], ah[i][3], ad);
                LDM_X4(al[i][0], al[i][1], al[i][2], al[i][3], ad + TILE_B);
            }
#pragma unroll
            for (int jp = 0; jp < 2; jp++) {
                uint32_t bd = stg + 2u * TILE_B +
                              (uint32_t)(wn * 32 + jp * 16 + lA) * ROWB + kso + sgo;
                LDM_X4(bh[2 * jp][0], bh[2 * jp + 1][0], bh[2 * jp][1], bh[2 * jp + 1][1], bd);
                LDM_X4(bl[2 * jp][0], bl[2 * jp + 1][0], bl[2 * jp][1], bl[2 * jp + 1][1],
                       bd + TILE_B);
            }
            // pass 1: ah*bh ; pass 2: al*bh ; pass 3: ah*bl
#pragma unroll
            for (int i = 0; i < 4; i++)
#pragma unroll
                for (int j = 0; j < 4; j++) mma16816(acc[i][j], ah[i], bh[j]);
#pragma unroll
            for (int i = 0; i < 4; i++)
#pragma unroll
                for (int j = 0; j < 4; j++) mma16816(acc[i][j], al[i], bh[j]);
#pragma unroll
            for (int i = 0; i < 4; i++)
#pragma unroll
                for (int j = 0; j < 4; j++) mma16816(acc[i][j], ah[i], bl[j]);
        }
        __syncthreads();
    }

    // ---- epilogue: bias (+residual), direct STG from fragments
    const int q  = lane >> 2;
    const int t4 = (lane & 3) * 2;
#pragma unroll
    for (int i = 0; i < 4; i++) {
        size_t r = m0 + wm * 64 + i * 16 + q;
#pragma unroll
        for (int j = 0; j < 4; j++) {
            size_t col = n0 + wn * 32 + j * 8 + t4;
            float bv = bias[col >> 3];
            float2 v0, v1;
            v0.x = acc[i][j][0] + bv; v0.y = acc[i][j][1] + bv;
            v1.x = acc[i][j][2] + bv; v1.y = acc[i][j][3] + bv;
            if (residual) {
                float2 r0 = *reinterpret_cast<const float2*>(residual + r * N + col);
                float2 r1 = *reinterpret_cast<const float2*>(residual + (r + 8) * N + col);
                v0.x += r0.x; v0.y += r0.y;
                v1.x += r1.x; v1.y += r1.y;
            }
            *reinterpret_cast<float2*>(C + r * N + col)       = v0;
            *reinterpret_cast<float2*>(C + (r + 8) * N + col) = v1;
        }
    }
}

// ---------------------------------------------------------------------------
// Per-batch attention: 8 heads, seq-len 8, dim 64.
// Emits attn weights (fp32) and Z as bf16 hi/lo split for the FC GEMM.
// ---------------------------------------------------------------------------
#define ROWSTR 516

__global__ __launch_bounds__(256)
void attn_kernel(const float* __restrict__ Yq, const float* __restrict__ Yk,
                 const float* __restrict__ Yv,
                 ushort_t* __restrict__ Zh, ushort_t* __restrict__ Zl,
                 float* __restrict__ attn_out)
{
    extern __shared__ float sm[];
    float* sQ = sm;
    float* sK = sm + 8 * ROWSTR;
    float* sV = sm + 16 * ROWSTR;

    int b   = blockIdx.x;
    int tid = threadIdx.x;

    const float4* q4 = (const float4*)(Yq + (size_t)b * 4096);
    const float4* k4 = (const float4*)(Yk + (size_t)b * 4096);
    const float4* v4 = (const float4*)(Yv + (size_t)b * 4096);
    for (int i = tid; i < 1024; i += 256) {
        int gg  = i >> 7;
        int off = i & 127;
        int d4  = gg * (ROWSTR / 4) + off;
        ((float4*)sQ)[d4] = q4[i];
        ((float4*)sK)[d4] = k4[i];
        ((float4*)sV)[d4] = v4[i];
    }
    __syncthreads();

    int w    = tid >> 5;
    int lane = tid & 31;
    int base = w * 64;
    int g1a  = lane >> 3;
    int g2   = lane & 7;
    int g1b  = g1a + 4;

    const float* qa = sQ + g1a * ROWSTR + base;
    const float* qb = sQ + g1b * ROWSTR + base;
    const float* kr = sK + g2  * ROWSTR + base;
    float s0 = 0.f, s1 = 0.f;
#pragma unroll 8
    for (int d = 0; d < 64; d++) {
        float kv = kr[d];
        s0 = fmaf(qa[d], kv, s0);
        s1 = fmaf(qb[d], kv, s1);
    }
    s0 *= 0.125f; s1 *= 0.125f;

    float m0 = s0, m1 = s1;
#pragma unroll
    for (int off = 4; off; off >>= 1) {
        m0 = fmaxf(m0, __shfl_xor_sync(0xffffffffu, m0, off));
        m1 = fmaxf(m1, __shfl_xor_sync(0xffffffffu, m1, off));
    }
    float e0 = __expf(s0 - m0), e1 = __expf(s1 - m1);
    float z0 = e0, z1 = e1;
#pragma unroll
    for (int off = 4; off; off >>= 1) {
        z0 += __shfl_xor_sync(0xffffffffu, z0, off);
        z1 += __shfl_xor_sync(0xffffffffu, z1, off);
    }
    float a0 = e0 / z0, a1 = e1 / z1;

    attn_out[(size_t)b * 512 + base + lane]      = a0;
    attn_out[(size_t)b * 512 + base + 32 + lane] = a1;

    __syncwarp();
    sQ[g1a * ROWSTR + base + g2] = a0;
    sQ[g1b * ROWSTR + base + g2] = a1;
    __syncwarp();

    size_t zb = (size_t)b * 4096 + base;
#pragma unroll
    for (int g1 = 0; g1 < 8; g1++) {
        const float* ar = sQ + g1 * ROWSTR + base;
        float acc0 = 0.f, acc1 = 0.f;
#pragma unroll
        for (int j = 0; j < 8; j++) {
            float a = ar[j];
            acc0 = fmaf(a, sV[j * ROWSTR + base + lane],      acc0);
            acc1 = fmaf(a, sV[j * ROWSTR + base + 32 + lane], acc1);
        }
        uint32_t u0 = __float_as_uint(acc0), u1 = __float_as_uint(acc1);
        size_t i0 = zb + g1 * 512 + lane;
        size_t i1 = i0 + 32;
        Zh[i0] = (ushort_t)(u0 >> 16);
        Zh[i1] = (ushort_t)(u1 >> 16);
        Zl[i0] = bf16_rn_bits(acc0 - __uint_as_float(u0 & 0xffff0000u));
        Zl[i1] = bf16_rn_bits(acc1 - __uint_as_float(u1 & 0xffff0000u));
    }
}

// ---------------------------------------------------------------------------
// Launch
// ---------------------------------------------------------------------------
extern "C" void kernel_launch(void* const* d_in, const int* in_sizes, int n_in,
                              void* d_out, int out_size) {
    const float* q    = (const float*)d_in[0];
    const float* k    = (const float*)d_in[1];
    const float* v    = (const float*)d_in[2];
    const float* w_q  = (const float*)d_in[3];
    const float* b_q  = (const float*)d_in[4];
    const float* w_k  = (const float*)d_in[5];
    const float* b_k  = (const float*)d_in[6];
    const float* w_v  = (const float*)d_in[7];
    const float* b_v  = (const float*)d_in[8];
    const float* w_fc = (const float*)d_in[9];
    const float* b_fc = (const float*)d_in[10];

    float* out = (float*)d_out;
    const size_t OUT_ELEMS  = (size_t)BATCH * CDIM;
    const size_t ATTN_ELEMS = (size_t)BATCH * 512;

    ushort_t *Wqh, *Wql, *Wkh, *Wkl, *Wvh, *Wvl, *Wfh, *Wfl;
    ushort_t *qh, *ql, *kh, *kl, *vh, *vl, *Zh, *Zl;
    float *Yq, *Yk, *Yv, *attnDummy;
    cudaGetSymbolAddress((void**)&Wqh, g_Wqh); cudaGetSymbolAddress((void**)&Wql, g_Wql);
    cudaGetSymbolAddress((void**)&Wkh, g_Wkh); cudaGetSymbolAddress((void**)&Wkl, g_Wkl);
    cudaGetSymbolAddress((void**)&Wvh, g_Wvh); cudaGetSymbolAddress((void**)&Wvl, g_Wvl);
    cudaGetSymbolAddress((void**)&Wfh, g_Wfh); cudaGetSymbolAddress((void**)&Wfl, g_Wfl);
    cudaGetSymbolAddress((void**)&qh,  g_qh);  cudaGetSymbolAddress((void**)&ql,  g_ql);
    cudaGetSymbolAddress((void**)&kh,  g_kh);  cudaGetSymbolAddress((void**)&kl,  g_kl);
    cudaGetSymbolAddress((void**)&vh,  g_vh);  cudaGetSymbolAddress((void**)&vl,  g_vl);
    cudaGetSymbolAddress((void**)&Zh,  g_Zh);  cudaGetSymbolAddress((void**)&Zl,  g_Zl);
    cudaGetSymbolAddress((void**)&Yq,  g_Yq);
    cudaGetSymbolAddress((void**)&Yk,  g_Yk);
    cudaGetSymbolAddress((void**)&Yv,  g_Yv);
    cudaGetSymbolAddress((void**)&attnDummy, g_attn_dummy);

    float* attn_out = ((size_t)out_size >= OUT_ELEMS + ATTN_ELEMS)
                          ? (out + OUT_ELEMS) : attnDummy;

    // 1) expand circulant weights fused with bf16 split
    expand_split_kernel<<<2048, 256>>>(w_q,  Wqh, Wql, 512, 128, 10);
    expand_split_kernel<<<2048, 256>>>(w_k,  Wkh, Wkl, 512, 128, 10);
    expand_split_kernel<<<2048, 256>>>(w_v,  Wvh, Wvl, 512, 128, 10);
    expand_split_kernel<<<2048, 256>>>(w_fc, Wfh, Wfl, 128, 512, 12);

    // 2) split activations
    const int N4 = BATCH * CDIM / 4;
    split_act_kernel<<<(N4 + 255) / 256, 256>>>((const float4*)q, qh, ql, N4);
    split_act_kernel<<<(N4 + 255) / 256, 256>>>((const float4*)k, kh, kl, N4);
    split_act_kernel<<<(N4 + 255) / 256, 256>>>((const float4*)v, vh, vl, N4);

    // 3) q/k/v projections
    cudaFuncSetAttribute(gemm_bf16ldm, cudaFuncAttributeMaxDynamicSharedMemorySize,
                         GEMM_SMEM_BYTES);
    dim3 gp(NPROJ / TN, BATCH / TM);           // (32, 64)
    gemm_bf16ldm<<<gp, 256, GEMM_SMEM_BYTES>>>(qh, ql, Wqh, Wql, Yq, NPROJ, KPROJ, b_q, nullptr);
    gemm_bf16ldm<<<gp, 256, GEMM_SMEM_BYTES>>>(kh, kl, Wkh, Wkl, Yk, NPROJ, KPROJ, b_k, nullptr);
    gemm_bf16ldm<<<gp, 256, GEMM_SMEM_BYTES>>>(vh, vl, Wvh, Wvl, Yv, NPROJ, KPROJ, b_v, nullptr);

    // 4) attention -> attn weights + Z (bf16 hi/lo)
    static const int attn_smem = 24 * ROWSTR * (int)sizeof(float);
    cudaFuncSetAttribute(attn_kernel, cudaFuncAttributeMaxDynamicSharedMemorySize,
                         attn_smem);
    attn_kernel<<<BATCH, 256, attn_smem>>>(Yq, Yk, Yv, Zh, Zl, attn_out);

    // 5) fc projection + bias + residual
    dim3 gf(NFC / TN, BATCH / TM);             // (8, 64)
    gemm_bf16ldm<<<gf, 256, GEMM_SMEM_BYTES>>>(Zh, Zl, Wfh, Wfl, out, NFC, KFC, b_fc, q);
}